// round 14
// baseline (speedup 1.0000x reference)
#include <cuda_runtime.h>
#include <cuda_fp16.h>
#include <cstdint>

#define N_NODES 20000
#define N_EDGES 320000
#define DK      256
#define M_PAD   20096   // 157 * 128
#define BN_EPS  1e-5f
#define NA_T    157     // agg tiles (128 nodes each)
#define NG1_T   628     // gemm1 tiles (128x64, NB=256)

// ---------------- static scratch ----------------
__device__ __half g_zh[M_PAD * DK];
__device__ __half g_th[M_PAD * DK];
__device__ __half g_hf16[M_PAD * DK];
__device__ int    g_deg[N_NODES];
__device__ int    g_offs[N_NODES + 1];
__device__ int    g_cursor[N_NODES];
__device__ int    g_csrc[N_EDGES];
__device__ __half g_wf16[622592];
// persistent-kernel sync state (zeroed in prep every launch)
__device__ int    g_counter[5];
__device__ int    g_aggflag[5 * NA_T];
__device__ int    g_g1done[5 * NA_T];
__device__ int    g_aggdone[5];

// ---------------- helpers ----------------
__device__ __forceinline__ uint32_t smem_u32(const void* p) {
    uint32_t a;
    asm("{ .reg .u64 t; cvta.to.shared.u64 t, %1; cvt.u32.u64 %0, t; }" : "=r"(a) : "l"(p));
    return a;
}
__device__ __forceinline__ uint32_t sw128(uint32_t off) { return off ^ ((off >> 3) & 0x70); }

__device__ __forceinline__ void ldm_x4(uint32_t& r0, uint32_t& r1, uint32_t& r2, uint32_t& r3,
                                       uint32_t addr) {
    asm volatile("ldmatrix.sync.aligned.m8n8.x4.shared.b16 {%0,%1,%2,%3}, [%4];"
                 : "=r"(r0), "=r"(r1), "=r"(r2), "=r"(r3) : "r"(addr));
}
__device__ __forceinline__ void mma_f16(float* d, const uint32_t* a, const uint32_t* b) {
    asm volatile(
        "mma.sync.aligned.m16n8k16.row.col.f32.f16.f16.f32 "
        "{%0,%1,%2,%3}, {%4,%5,%6,%7}, {%8,%9}, {%0,%1,%2,%3};"
        : "+f"(d[0]), "+f"(d[1]), "+f"(d[2]), "+f"(d[3])
        : "r"(a[0]), "r"(a[1]), "r"(a[2]), "r"(a[3]), "r"(b[0]), "r"(b[1]));
}

// ---------------- CSR build ----------------
__global__ void scan_kernel() {
    __shared__ int carry;
    __shared__ int wsum[32];
    int tid = threadIdx.x, lane = tid & 31, wid = tid >> 5;
    if (tid == 0) carry = 0;
    __syncthreads();
    for (int base = 0; base < N_NODES; base += 1024) {
        int i = base + tid;
        int v = (i < N_NODES) ? g_deg[i] : 0;
        int s = v;
        #pragma unroll
        for (int d = 1; d < 32; d <<= 1) {
            int t = __shfl_up_sync(0xffffffffu, s, d);
            if (lane >= d) s += t;
        }
        if (lane == 31) wsum[wid] = s;
        __syncthreads();
        if (wid == 0) {
            int ws = wsum[lane];
            #pragma unroll
            for (int d = 1; d < 32; d <<= 1) {
                int t = __shfl_up_sync(0xffffffffu, ws, d);
                if (lane >= d) ws += t;
            }
            wsum[lane] = ws;
        }
        __syncthreads();
        int excl = s - v + (wid > 0 ? wsum[wid - 1] : 0) + carry;
        if (i < N_NODES) { g_offs[i] = excl; g_cursor[i] = excl; }
        int total = wsum[31];
        __syncthreads();
        if (tid == 0) carry += total;
        __syncthreads();
    }
    if (tid == 0) g_offs[N_NODES] = carry;
}

__global__ void fill_kernel(const int* __restrict__ src, const int* __restrict__ dst) {
    int e = blockIdx.x * blockDim.x + threadIdx.x;
    if (e < N_NODES) g_deg[e] = 0;   // re-zero for next launch replay
    if (e < N_EDGES) {
        int d = dst[e];
        int pos = atomicAdd(&g_cursor[d], 1);
        g_csrc[pos] = src[e];
    }
}

// ---------------- prep: weight transpose + x pack + edge count + flag zero ----------------
#define PR_W   622592
#define PR_X   (PR_W + 1280000)
#define PR_C   (PR_X + N_EDGES)
#define PR_Z   (PR_C + 1580)
__global__ void prep_kernel(const float* __restrict__ W1, const float* __restrict__ W2a,
                            const float* __restrict__ W2l, const float* __restrict__ x,
                            const int* __restrict__ dst) {
    int i = blockIdx.x * blockDim.x + threadIdx.x;
    if (i < PR_W) {
        const float* src;
        int local, N;
        if (i < 327680)      { src = W1  + (size_t)(i >> 16) * 65536;            local = i & 65535;  N = 256; }
        else if (i < 589824) { src = W2a + (size_t)((i - 327680) >> 16) * 65536; local = (i - 327680) & 65535; N = 256; }
        else                 { src = W2l;                                        local = i - 589824; N = 128; }
        int n = local >> 8, k = local & 255;
        g_wf16[i] = __float2half_rn(src[k * N + n]);
    } else if (i < PR_X) {
        int j = i - PR_W;
        float4 v = ((const float4*)x)[j];
        __half2 p0 = __float22half2_rn(make_float2(v.x, v.y));
        __half2 p1 = __float22half2_rn(make_float2(v.z, v.w));
        ((uint2*)g_hf16)[j] = make_uint2(*(uint32_t*)&p0, *(uint32_t*)&p1);
    } else if (i < PR_C) {
        int e = i - PR_X;
        atomicAdd(&g_deg[dst[e]], 1);
    } else if (i < PR_Z) {
        int j = i - PR_C;
        if (j < 5)                 g_counter[j] = 0;
        else if (j < 5 + 785)      g_aggflag[j - 5] = 0;
        else if (j < 5 + 1570)     g_g1done[j - 790] = 0;
        else                       g_aggdone[j - 1575] = 0;
    }
}

// ---------------- agg tile: 128 nodes, warp-per-node ----------------
__device__ void agg_tile(int t, const __half* __restrict__ h, __half* __restrict__ z, float e1) {
    int wid = threadIdx.x >> 5, lane = threadIdx.x & 31;
    const uint4* h4 = (const uint4*)h;
    for (int i = wid; i < 128; i += 8) {
        int gw = t * 128 + i;
        if (gw >= N_NODES) break;
        uint4 sv = h4[(size_t)gw * 32 + lane];
        float2 a0 = __half22float2(*(__half2*)&sv.x);
        float2 a1 = __half22float2(*(__half2*)&sv.y);
        float2 a2 = __half22float2(*(__half2*)&sv.z);
        float2 a3 = __half22float2(*(__half2*)&sv.w);
        a0.x *= e1; a0.y *= e1; a1.x *= e1; a1.y *= e1;
        a2.x *= e1; a2.y *= e1; a3.x *= e1; a3.y *= e1;
        int beg = g_offs[gw], end = g_offs[gw + 1];
        int j = beg;
        for (; j + 1 < end; j += 2) {
            int u0 = g_csrc[j], u1 = g_csrc[j + 1];
            uint4 b = h4[(size_t)u0 * 32 + lane];
            uint4 c = h4[(size_t)u1 * 32 + lane];
            float2 tt;
            tt = __half22float2(*(__half2*)&b.x); a0.x += tt.x; a0.y += tt.y;
            tt = __half22float2(*(__half2*)&b.y); a1.x += tt.x; a1.y += tt.y;
            tt = __half22float2(*(__half2*)&b.z); a2.x += tt.x; a2.y += tt.y;
            tt = __half22float2(*(__half2*)&b.w); a3.x += tt.x; a3.y += tt.y;
            tt = __half22float2(*(__half2*)&c.x); a0.x += tt.x; a0.y += tt.y;
            tt = __half22float2(*(__half2*)&c.y); a1.x += tt.x; a1.y += tt.y;
            tt = __half22float2(*(__half2*)&c.z); a2.x += tt.x; a2.y += tt.y;
            tt = __half22float2(*(__half2*)&c.w); a3.x += tt.x; a3.y += tt.y;
        }
        if (j < end) {
            int u0 = g_csrc[j];
            uint4 b = h4[(size_t)u0 * 32 + lane];
            float2 tt;
            tt = __half22float2(*(__half2*)&b.x); a0.x += tt.x; a0.y += tt.y;
            tt = __half22float2(*(__half2*)&b.y); a1.x += tt.x; a1.y += tt.y;
            tt = __half22float2(*(__half2*)&b.z); a2.x += tt.x; a2.y += tt.y;
            tt = __half22float2(*(__half2*)&b.w); a3.x += tt.x; a3.y += tt.y;
        }
        const float S = 0.0625f;
        a0.x *= S; a0.y *= S; a1.x *= S; a1.y *= S;
        a2.x *= S; a2.y *= S; a3.x *= S; a3.y *= S;
        __half2 o0 = __float22half2_rn(a0), o1 = __float22half2_rn(a1);
        __half2 o2 = __float22half2_rn(a2), o3 = __float22half2_rn(a3);
        ((uint4*)z)[(size_t)gw * 32 + lane] =
            make_uint4(*(uint32_t*)&o0, *(uint32_t*)&o1, *(uint32_t*)&o2, *(uint32_t*)&o3);
    }
}

// ---------------- gemm tile 128(M)x64(N), single-term fp16 ----------------
template <int NB, int EPI>
__device__ void gemm_tile(char* smem, uint32_t sb,
                          const __half* __restrict__ A, const __half* __restrict__ B,
                          float* __restrict__ C, __half* __restrict__ Ch,
                          const float* __restrict__ bias,
                          const float* __restrict__ bn_g, const float* __restrict__ bn_b,
                          const float* __restrict__ bn_m, const float* __restrict__ bn_v,
                          float rs, int bm, int bn) {
    constexpr int OFF_A  = 0;
    constexpr int OFF_B  = 16384;
    constexpr int OFF_SC = 24576;
    constexpr int OFF_SH = 24832;
    const int tid = threadIdx.x, wid = tid >> 5, lane = tid & 31;
    const int warpM = wid >> 1, warpN = wid & 1;

    float* SC = (float*)(smem + OFF_SC);
    float* SH = (float*)(smem + OFF_SH);
    if (tid < 64) {
        int n = bn + tid;
        if (EPI == 1) {
            float s = bn_g[n] * rsqrtf(bn_v[n] + BN_EPS);
            SC[tid] = s;
            SH[tid] = ((bias[n] - bn_m[n]) * s + bn_b[n]) * rs;
        } else if (EPI == 0) {
            SC[tid] = 1.0f;
            SH[tid] = bias[n] * rs;
        } else {
            SC[tid] = rs;
            SH[tid] = bias[n];
        }
    }

    float acc[2][4][4];
    #pragma unroll
    for (int f = 0; f < 2; f++)
        #pragma unroll
        for (int j = 0; j < 4; j++)
            #pragma unroll
            for (int q = 0; q < 4; q++) acc[f][j][q] = 0.0f;

    const int mbase = warpM * 32, nwbase = warpN * 32;

    for (int kc = 0; kc < 4; kc++) {
        __syncthreads();
        #pragma unroll
        for (int it = 0; it < 4; it++) {
            int item = tid + it * 256;
            int r = item >> 3, g = item & 7;
            uint4 v = *(const uint4*)(A + (size_t)(bm + r) * DK + kc * 64 + g * 8);
            *(uint4*)(smem + OFF_A + sw128((uint32_t)(r * 128 + g * 16))) = v;
        }
        #pragma unroll
        for (int it = 0; it < 2; it++) {
            int item = tid + it * 256;
            int n = item >> 3, g = item & 7;
            uint4 v = *(const uint4*)(B + (size_t)(bn + n) * DK + kc * 64 + g * 8);
            *(uint4*)(smem + OFF_B + sw128((uint32_t)(n * 128 + g * 16))) = v;
        }
        __syncthreads();

        #pragma unroll
        for (int kk = 0; kk < 4; kk++) {
            uint32_t a[2][4];
            int arow = mbase + (lane & 15);
            uint32_t akb = kk * 32 + ((lane & 16) ? 16 : 0);
            #pragma unroll
            for (int f = 0; f < 2; f++) {
                uint32_t off = sw128((uint32_t)((arow + f * 16) * 128) + akb);
                ldm_x4(a[f][0], a[f][1], a[f][2], a[f][3], sb + OFF_A + off);
            }
            int brow = nwbase + (lane & 7) + ((lane & 16) ? 8 : 0);
            uint32_t bkb = kk * 32 + ((lane & 8) ? 16 : 0);
            #pragma unroll
            for (int jp = 0; jp < 2; jp++) {
                uint32_t off = sw128((uint32_t)((brow + jp * 16) * 128) + bkb);
                uint32_t bf[4];
                ldm_x4(bf[0], bf[1], bf[2], bf[3], sb + OFF_B + off);
                #pragma unroll
                for (int f = 0; f < 2; f++) {
                    mma_f16(acc[f][2 * jp],     a[f], bf);
                    mma_f16(acc[f][2 * jp + 1], a[f], bf + 2);
                }
            }
        }
    }

    #pragma unroll
    for (int f = 0; f < 2; f++) {
        int r0 = bm + mbase + f * 16 + (lane >> 2);
        #pragma unroll
        for (int j = 0; j < 4; j++) {
            int nloc = nwbase + j * 8 + (lane & 3) * 2;
            float s0 = SC[nloc], s1 = SC[nloc + 1];
            float t0 = SH[nloc], t1 = SH[nloc + 1];
            float v0 = acc[f][j][0] * s0 + t0;
            float v1 = acc[f][j][1] * s1 + t1;
            float v2 = acc[f][j][2] * s0 + t0;
            float v3 = acc[f][j][3] * s1 + t1;
            if (EPI != 2) {
                v0 = fmaxf(v0, 0.0f); v1 = fmaxf(v1, 0.0f);
                v2 = fmaxf(v2, 0.0f); v3 = fmaxf(v3, 0.0f);
            }
            int col = bn + nloc;
            if (EPI == 2) {
                if (r0 < N_NODES)
                    *(float2*)(C + (size_t)r0 * NB + col) = make_float2(v0, v1);
                if (r0 + 8 < N_NODES)
                    *(float2*)(C + (size_t)(r0 + 8) * NB + col) = make_float2(v2, v3);
            } else {
                __half2 p0 = __float22half2_rn(make_float2(v0, v1));
                __half2 p1 = __float22half2_rn(make_float2(v2, v3));
                if (r0 < N_NODES)
                    *(__half2*)(Ch + (size_t)r0 * NB + col) = p0;
                if (r0 + 8 < N_NODES)
                    *(__half2*)(Ch + (size_t)(r0 + 8) * NB + col) = p1;
            }
        }
    }
}

// ---------------- persistent per-layer kernel ----------------
// Tile stream: [0,157) agg ; [157,785) gemm1 (m=g>>2, n=g&3) ; rest gemm2.
// Waits point only to earlier-grabbed tiles -> deadlock-free.
template <int LAST>
__global__ __launch_bounds__(256, 2)
void layer_kernel(const __half* __restrict__ hf, __half* __restrict__ zh,
                  __half* __restrict__ th, __half* __restrict__ hout, float* __restrict__ fout,
                  const __half* __restrict__ w1, const __half* __restrict__ w2,
                  const float* __restrict__ b1, const float* __restrict__ b2,
                  const float* __restrict__ bng, const float* __restrict__ bnb,
                  const float* __restrict__ bnm, const float* __restrict__ bnv,
                  const float* __restrict__ eps, int layer, float rs1, float rs2,
                  int* counter, int* aggflag, int* g1done, int* aggdone) {
    extern __shared__ __align__(1024) char smem[];
    __shared__ int s_t;
    const int tid = threadIdx.x;
    const uint32_t sb = smem_u32(smem);
    const int NG2 = LAST ? 314 : 628;
    const int NT = NA_T + NG1_T + NG2;

    for (;;) {
        if (tid == 0) s_t = atomicAdd(counter, 1);
        __syncthreads();
        int t = s_t;
        if (t >= NT) return;

        if (t < NA_T) {
            agg_tile(t, hf, zh, 1.0f + __ldg(&eps[layer]));
            __syncthreads();
            if (tid == 0) {
                __threadfence();
                atomicExch(&aggflag[t], 1);
                atomicAdd(aggdone, 1);
            }
        } else if (t < NA_T + NG1_T) {
            int g = t - NA_T;
            int m = g >> 2, n = g & 3;
            if (tid == 0) {
                while (atomicAdd(&aggflag[m], 0) == 0) __nanosleep(100);
                __threadfence();
            }
            __syncthreads();
            gemm_tile<256, 0>(smem, sb, zh, w1, nullptr, th, b1,
                              nullptr, nullptr, nullptr, nullptr, rs1, m * 128, n * 64);
            __syncthreads();
            if (tid == 0) { __threadfence(); atomicAdd(&g1done[m], 1); }
        } else {
            int g = t - NA_T - NG1_T;
            if (LAST) {
                int m = g >> 1, n = g & 1;
                if (tid == 0) {
                    while (atomicAdd(&g1done[m], 0) < 4 || atomicAdd(aggdone, 0) < NA_T)
                        __nanosleep(100);
                    __threadfence();
                }
                __syncthreads();
                gemm_tile<128, 2>(smem, sb, th, w2, fout, nullptr, b2,
                                  nullptr, nullptr, nullptr, nullptr, rs2, m * 128, n * 64);
            } else {
                int m = g >> 2, n = g & 3;
                if (tid == 0) {
                    while (atomicAdd(&g1done[m], 0) < 4 || atomicAdd(aggdone, 0) < NA_T)
                        __nanosleep(100);
                    __threadfence();
                }
                __syncthreads();
                gemm_tile<256, 1>(smem, sb, th, w2, nullptr, hout, b2,
                                  bng, bnb, bnm, bnv, rs2, m * 128, n * 64);
            }
        }
        __syncthreads();
    }
}

// ---------------- launch ----------------
extern "C" void kernel_launch(void* const* d_in, const int* in_sizes, int n_in,
                              void* d_out, int out_size) {
    const float* x    = (const float*)d_in[0];
    const int*   ei   = (const int*)d_in[1];
    const float* W1   = (const float*)d_in[2];
    const float* b1   = (const float*)d_in[3];
    const float* W2a  = (const float*)d_in[4];
    const float* b2a  = (const float*)d_in[5];
    const float* W2l  = (const float*)d_in[6];
    const float* b2l  = (const float*)d_in[7];
    const float* eps  = (const float*)d_in[8];
    const float* bng  = (const float*)d_in[9];
    const float* bnb  = (const float*)d_in[10];
    const float* bnm  = (const float*)d_in[11];
    const float* bnv  = (const float*)d_in[12];
    float* out = (float*)d_out;

    void* p;
    cudaGetSymbolAddress(&p, g_zh);      __half* zh = (__half*)p;
    cudaGetSymbolAddress(&p, g_th);      __half* th = (__half*)p;
    cudaGetSymbolAddress(&p, g_hf16);    __half* hf = (__half*)p;
    cudaGetSymbolAddress(&p, g_wf16);    const __half* wf = (const __half*)p;
    cudaGetSymbolAddress(&p, g_counter); int* cnt = (int*)p;
    cudaGetSymbolAddress(&p, g_aggflag); int* afl = (int*)p;
    cudaGetSymbolAddress(&p, g_g1done);  int* g1d = (int*)p;
    cudaGetSymbolAddress(&p, g_aggdone); int* agd = (int*)p;

    const int* srcp = ei;
    const int* dstp = ei + N_EDGES;

    const int SMEM = 25088 + 256;
    cudaFuncSetAttribute(layer_kernel<0>, cudaFuncAttributeMaxDynamicSharedMemorySize, SMEM);
    cudaFuncSetAttribute(layer_kernel<1>, cudaFuncAttributeMaxDynamicSharedMemorySize, SMEM);

    // prep (weights + pack x + edge count + zero sync state), then scan, then fill
    prep_kernel<<<(PR_Z + 255) / 256, 256>>>(W1, W2a, W2l, x, dstp);
    scan_kernel<<<1, 1024>>>();
    fill_kernel<<<(N_EDGES + 255) / 256, 256>>>(srcp, dstp);

    const float RS[5] = {1.0f / 16, 1.0f / 256, 1.0f / 4096, 1.0f / 65536, 1.0f / 1048576};

    for (int i = 0; i < 4; i++) {
        layer_kernel<0><<<296, 256, SMEM>>>(
            hf, zh, th, hf, nullptr,
            wf + (size_t)i * 65536, wf + (size_t)(5 + i) * 65536,
            b1 + i * 256, b2a + i * 256,
            bng + i * 256, bnb + i * 256, bnm + i * 256, bnv + i * 256,
            eps, i, RS[i], RS[i],
            cnt + i, afl + i * NA_T, g1d + i * NA_T, agd + i);
    }
    layer_kernel<1><<<296, 256, SMEM>>>(
        hf, zh, th, nullptr, out,
        wf + (size_t)4 * 65536, wf + (size_t)9 * 65536,
        b1 + 4 * 256, b2l,
        nullptr, nullptr, nullptr, nullptr,
        eps, 4, RS[4], 1048576.0f,
        cnt + 4, afl + 4 * NA_T, g1d + 4 * NA_T, agd + 4);
}

// round 15
// speedup vs baseline: 1.0118x; 1.0118x over previous
#include <cuda_runtime.h>
#include <cuda_fp16.h>
#include <cstdint>

#define N_NODES 20000
#define N_EDGES 320000
#define DK      256
#define M_PAD   20096
#define BN_EPS  1e-5f

// ---------------- static scratch ----------------
__device__ __half g_th[M_PAD * DK];     // hidden after first MLP layer
__device__ __half g_hf16[M_PAD * DK];   // layer input mirror (x or h)
__device__ int    g_deg[N_NODES];
__device__ int    g_offs[N_NODES + 1];
__device__ int    g_cursor[N_NODES];
__device__ int    g_csrc[N_EDGES];
// transposed fp16 weights: layout [n][k], K-major (K=256)
__device__ __half g_wf16[622592];

// ---------------- helpers ----------------
__device__ __forceinline__ uint32_t smem_u32(const void* p) {
    uint32_t a;
    asm("{ .reg .u64 t; cvta.to.shared.u64 t, %1; cvt.u32.u64 %0, t; }" : "=r"(a) : "l"(p));
    return a;
}
__device__ __forceinline__ uint32_t sw128(uint32_t off) { return off ^ ((off >> 3) & 0x70); }

__device__ __forceinline__ void ldm_x4(uint32_t& r0, uint32_t& r1, uint32_t& r2, uint32_t& r3,
                                       uint32_t addr) {
    asm volatile("ldmatrix.sync.aligned.m8n8.x4.shared.b16 {%0,%1,%2,%3}, [%4];"
                 : "=r"(r0), "=r"(r1), "=r"(r2), "=r"(r3) : "r"(addr));
}
__device__ __forceinline__ void mma_f16(float* d, const uint32_t* a, const uint32_t* b) {
    asm volatile(
        "mma.sync.aligned.m16n8k16.row.col.f32.f16.f16.f32 "
        "{%0,%1,%2,%3}, {%4,%5,%6,%7}, {%8,%9}, {%0,%1,%2,%3};"
        : "+f"(d[0]), "+f"(d[1]), "+f"(d[2]), "+f"(d[3])
        : "r"(a[0]), "r"(a[1]), "r"(a[2]), "r"(a[3]), "r"(b[0]), "r"(b[1]));
}

// ---------------- CSR build ----------------
__global__ void scan_kernel() {
    __shared__ int carry;
    __shared__ int wsum[32];
    int tid = threadIdx.x, lane = tid & 31, wid = tid >> 5;
    if (tid == 0) carry = 0;
    __syncthreads();
    for (int base = 0; base < N_NODES; base += 1024) {
        int i = base + tid;
        int v = (i < N_NODES) ? g_deg[i] : 0;
        int s = v;
        #pragma unroll
        for (int d = 1; d < 32; d <<= 1) {
            int t = __shfl_up_sync(0xffffffffu, s, d);
            if (lane >= d) s += t;
        }
        if (lane == 31) wsum[wid] = s;
        __syncthreads();
        if (wid == 0) {
            int ws = wsum[lane];
            #pragma unroll
            for (int d = 1; d < 32; d <<= 1) {
                int t = __shfl_up_sync(0xffffffffu, ws, d);
                if (lane >= d) ws += t;
            }
            wsum[lane] = ws;
        }
        __syncthreads();
        int excl = s - v + (wid > 0 ? wsum[wid - 1] : 0) + carry;
        if (i < N_NODES) { g_offs[i] = excl; g_cursor[i] = excl; }
        int total = wsum[31];
        __syncthreads();
        if (tid == 0) carry += total;
        __syncthreads();
    }
    if (tid == 0) g_offs[N_NODES] = carry;
}

__global__ void fill_kernel(const int* __restrict__ src, const int* __restrict__ dst) {
    int e = blockIdx.x * blockDim.x + threadIdx.x;
    if (e < N_NODES) g_deg[e] = 0;
    if (e < N_EDGES) {
        int d = dst[e];
        int pos = atomicAdd(&g_cursor[d], 1);
        g_csrc[pos] = src[e];
    }
}

// ---------------- prep: weight transpose + x pack + edge count ----------------
#define PR_W   622592
#define PR_X   (PR_W + 1280000)
#define PR_C   (PR_X + N_EDGES)
__global__ void prep_kernel(const float* __restrict__ W1, const float* __restrict__ W2a,
                            const float* __restrict__ W2l, const float* __restrict__ x,
                            const int* __restrict__ dst) {
    int i = blockIdx.x * blockDim.x + threadIdx.x;
    if (i < PR_W) {
        const float* src;
        int local, N;
        if (i < 327680)      { src = W1  + (size_t)(i >> 16) * 65536;            local = i & 65535;  N = 256; }
        else if (i < 589824) { src = W2a + (size_t)((i - 327680) >> 16) * 65536; local = (i - 327680) & 65535; N = 256; }
        else                 { src = W2l;                                        local = i - 589824; N = 128; }
        int n = local >> 8, k = local & 255;
        g_wf16[i] = __float2half_rn(src[k * N + n]);
    } else if (i < PR_X) {
        int j = i - PR_W;
        float4 v = ((const float4*)x)[j];
        __half2 p0 = __float22half2_rn(make_float2(v.x, v.y));
        __half2 p1 = __float22half2_rn(make_float2(v.z, v.w));
        ((uint2*)g_hf16)[j] = make_uint2(*(uint32_t*)&p0, *(uint32_t*)&p1);
    } else if (i < PR_C) {
        int e = i - PR_X;
        atomicAdd(&g_deg[dst[e]], 1);
    }
}

// ---------------- fused agg + gemm1: one CTA = 128 rows x full 256 N ----------------
// Phase 1: aggregate own 128 rows (fp32 acc, x1/16 scale) straight into SMEM A (SW128, 4 K-chunks).
// Phase 2: two 128x128 GEMM passes vs w1; epilogue relu(acc + b1*rs) -> th (fp16).
__global__ __launch_bounds__(256, 2)
void aggemm_kernel(const __half* __restrict__ hf, const __half* __restrict__ w1,
                   __half* __restrict__ th, const float* __restrict__ b1,
                   const float* __restrict__ eps, int layer, float rs) {
    extern __shared__ __align__(1024) char smem[];
    constexpr int OFF_A  = 0;        // 128 x 256 f16, as 4 chunks of 128x64 SW128 = 65536
    constexpr int OFF_B  = 65536;    // 128 x 64 f16 = 16384
    constexpr int OFF_SH = 81920;    // 256 floats
    const int tid = threadIdx.x, wid = tid >> 5, lane = tid & 31;
    const int warpM = wid >> 1, warpN = wid & 1;
    const int bm = blockIdx.x * 128;
    const uint32_t sb = smem_u32(smem);

    float* SH = (float*)(smem + OFF_SH);
    SH[tid] = __ldg(&b1[tid]) * rs;

    // ---- phase 1: aggregation into SMEM A ----
    {
        float e1 = 1.0f + __ldg(&eps[layer]);
        const uint4* h4 = (const uint4*)hf;
        int chunk = lane >> 3;
        for (int i = wid; i < 128; i += 8) {
            int gw = bm + i;
            if (gw >= N_NODES) break;
            uint4 sv = h4[(size_t)gw * 32 + lane];
            float2 a0 = __half22float2(*(__half2*)&sv.x);
            float2 a1 = __half22float2(*(__half2*)&sv.y);
            float2 a2 = __half22float2(*(__half2*)&sv.z);
            float2 a3 = __half22float2(*(__half2*)&sv.w);
            a0.x *= e1; a0.y *= e1; a1.x *= e1; a1.y *= e1;
            a2.x *= e1; a2.y *= e1; a3.x *= e1; a3.y *= e1;
            int beg = g_offs[gw], end = g_offs[gw + 1];
            int j = beg;
            for (; j + 1 < end; j += 2) {
                int u0 = g_csrc[j], u1 = g_csrc[j + 1];
                uint4 b = h4[(size_t)u0 * 32 + lane];
                uint4 c = h4[(size_t)u1 * 32 + lane];
                float2 tt;
                tt = __half22float2(*(__half2*)&b.x); a0.x += tt.x; a0.y += tt.y;
                tt = __half22float2(*(__half2*)&b.y); a1.x += tt.x; a1.y += tt.y;
                tt = __half22float2(*(__half2*)&b.z); a2.x += tt.x; a2.y += tt.y;
                tt = __half22float2(*(__half2*)&b.w); a3.x += tt.x; a3.y += tt.y;
                tt = __half22float2(*(__half2*)&c.x); a0.x += tt.x; a0.y += tt.y;
                tt = __half22float2(*(__half2*)&c.y); a1.x += tt.x; a1.y += tt.y;
                tt = __half22float2(*(__half2*)&c.z); a2.x += tt.x; a2.y += tt.y;
                tt = __half22float2(*(__half2*)&c.w); a3.x += tt.x; a3.y += tt.y;
            }
            if (j < end) {
                int u0 = g_csrc[j];
                uint4 b = h4[(size_t)u0 * 32 + lane];
                float2 tt;
                tt = __half22float2(*(__half2*)&b.x); a0.x += tt.x; a0.y += tt.y;
                tt = __half22float2(*(__half2*)&b.y); a1.x += tt.x; a1.y += tt.y;
                tt = __half22float2(*(__half2*)&b.z); a2.x += tt.x; a2.y += tt.y;
                tt = __half22float2(*(__half2*)&b.w); a3.x += tt.x; a3.y += tt.y;
            }
            const float S = 0.0625f;
            a0.x *= S; a0.y *= S; a1.x *= S; a1.y *= S;
            a2.x *= S; a2.y *= S; a3.x *= S; a3.y *= S;
            __half2 o0 = __float22half2_rn(a0), o1 = __float22half2_rn(a1);
            __half2 o2 = __float22half2_rn(a2), o3 = __float22half2_rn(a3);
            uint32_t off = sw128((uint32_t)(i * 128 + (lane & 7) * 16));
            *(uint4*)(smem + OFF_A + chunk * 16384 + off) =
                make_uint4(*(uint32_t*)&o0, *(uint32_t*)&o1, *(uint32_t*)&o2, *(uint32_t*)&o3);
        }
    }
    __syncthreads();

    // ---- phase 2: GEMM, two 128x128 passes ----
    const int mbase = warpM * 32, nwbase = warpN * 64;
    #pragma unroll
    for (int pass = 0; pass < 2; pass++) {
        float acc[2][8][4];
        #pragma unroll
        for (int f = 0; f < 2; f++)
            #pragma unroll
            for (int j = 0; j < 8; j++)
                #pragma unroll
                for (int q = 0; q < 4; q++) acc[f][j][q] = 0.0f;

        for (int kc = 0; kc < 4; kc++) {
            __syncthreads();
            // stage B: w1 rows pass*128 + [0,128), kc chunk
            #pragma unroll
            for (int it = 0; it < 4; it++) {
                int item = tid + it * 256;
                int n = item >> 3, g = item & 7;
                uint4 v = *(const uint4*)(w1 + (size_t)(pass * 128 + n) * DK + kc * 64 + g * 8);
                *(uint4*)(smem + OFF_B + sw128((uint32_t)(n * 128 + g * 16))) = v;
            }
            __syncthreads();

            const uint32_t abase = sb + OFF_A + kc * 16384;
            #pragma unroll
            for (int kk = 0; kk < 4; kk++) {
                uint32_t a[2][4];
                int arow = mbase + (lane & 15);
                uint32_t akb = kk * 32 + ((lane & 16) ? 16 : 0);
                #pragma unroll
                for (int f = 0; f < 2; f++) {
                    uint32_t off = sw128((uint32_t)((arow + f * 16) * 128) + akb);
                    ldm_x4(a[f][0], a[f][1], a[f][2], a[f][3], abase + off);
                }
                int brow = nwbase + (lane & 7) + ((lane & 16) ? 8 : 0);
                uint32_t bkb = kk * 32 + ((lane & 8) ? 16 : 0);
                #pragma unroll
                for (int jp = 0; jp < 4; jp++) {
                    uint32_t off = sw128((uint32_t)((brow + jp * 16) * 128) + bkb);
                    uint32_t bf[4];
                    ldm_x4(bf[0], bf[1], bf[2], bf[3], sb + OFF_B + off);
                    #pragma unroll
                    for (int f = 0; f < 2; f++) {
                        mma_f16(acc[f][2 * jp],     a[f], bf);
                        mma_f16(acc[f][2 * jp + 1], a[f], bf + 2);
                    }
                }
            }
        }

        // epilogue (EPI0): relu(acc + b1*rs) -> th fp16
        #pragma unroll
        for (int f = 0; f < 2; f++) {
            int r0 = bm + mbase + f * 16 + (lane >> 2);
            #pragma unroll
            for (int j = 0; j < 8; j++) {
                int nloc = nwbase + j * 8 + (lane & 3) * 2;
                int col = pass * 128 + nloc;
                float t0 = SH[col], t1 = SH[col + 1];
                float v0 = fmaxf(acc[f][j][0] + t0, 0.0f);
                float v1 = fmaxf(acc[f][j][1] + t1, 0.0f);
                float v2 = fmaxf(acc[f][j][2] + t0, 0.0f);
                float v3 = fmaxf(acc[f][j][3] + t1, 0.0f);
                __half2 p0 = __float22half2_rn(make_float2(v0, v1));
                __half2 p1 = __float22half2_rn(make_float2(v2, v3));
                if (r0 < N_NODES)
                    *(__half2*)(th + (size_t)r0 * 256 + col) = p0;
                if (r0 + 8 < N_NODES)
                    *(__half2*)(th + (size_t)(r0 + 8) * 256 + col) = p1;
            }
        }
    }
}

// ---------------- gemm2: tile 128(M)x64(N), single-term fp16 (R11 verbatim) ----------------
// EPI 1: relu(BN(acc+bias)) -> f16 ; EPI 2: acc*rs + bias -> f32
template <int NB, int EPI>
__global__ __launch_bounds__(256, 2)
void gemm_hmma(const __half* __restrict__ A, const __half* __restrict__ B,
               float* __restrict__ C, __half* __restrict__ Ch,
               const float* __restrict__ bias,
               const float* __restrict__ bn_g, const float* __restrict__ bn_b,
               const float* __restrict__ bn_m, const float* __restrict__ bn_v,
               float rs) {
    extern __shared__ __align__(1024) char smem[];
    constexpr int OFF_A  = 0;
    constexpr int OFF_B  = 16384;
    constexpr int OFF_SC = 24576;
    constexpr int OFF_SH = 24832;

    const int tid = threadIdx.x, wid = tid >> 5, lane = tid & 31;
    const int warpM = wid >> 1, warpN = wid & 1;
    const int bm = blockIdx.y * 128, bn = blockIdx.x * 64;
    const uint32_t sb = smem_u32(smem);

    float* SC = (float*)(smem + OFF_SC);
    float* SH = (float*)(smem + OFF_SH);
    if (tid < 64) {
        int n = bn + tid;
        if (EPI == 1) {
            float s = bn_g[n] * rsqrtf(bn_v[n] + BN_EPS);
            SC[tid] = s;
            SH[tid] = ((bias[n] - bn_m[n]) * s + bn_b[n]) * rs;
        } else {
            SC[tid] = rs;
            SH[tid] = bias[n];
        }
    }

    float acc[2][4][4];
    #pragma unroll
    for (int f = 0; f < 2; f++)
        #pragma unroll
        for (int j = 0; j < 4; j++)
            #pragma unroll
            for (int q = 0; q < 4; q++) acc[f][j][q] = 0.0f;

    const int mbase = warpM * 32, nwbase = warpN * 32;

    for (int kc = 0; kc < 4; kc++) {
        __syncthreads();
        #pragma unroll
        for (int it = 0; it < 4; it++) {
            int item = tid + it * 256;
            int r = item >> 3, g = item & 7;
            uint4 v = *(const uint4*)(A + (size_t)(bm + r) * DK + kc * 64 + g * 8);
            *(uint4*)(smem + OFF_A + sw128((uint32_t)(r * 128 + g * 16))) = v;
        }
        #pragma unroll
        for (int it = 0; it < 2; it++) {
            int item = tid + it * 256;
            int n = item >> 3, g = item & 7;
            uint4 v = *(const uint4*)(B + (size_t)(bn + n) * DK + kc * 64 + g * 8);
            *(uint4*)(smem + OFF_B + sw128((uint32_t)(n * 128 + g * 16))) = v;
        }
        __syncthreads();

        #pragma unroll
        for (int kk = 0; kk < 4; kk++) {
            uint32_t a[2][4];
            int arow = mbase + (lane & 15);
            uint32_t akb = kk * 32 + ((lane & 16) ? 16 : 0);
            #pragma unroll
            for (int f = 0; f < 2; f++) {
                uint32_t off = sw128((uint32_t)((arow + f * 16) * 128) + akb);
                ldm_x4(a[f][0], a[f][1], a[f][2], a[f][3], sb + OFF_A + off);
            }
            int brow = nwbase + (lane & 7) + ((lane & 16) ? 8 : 0);
            uint32_t bkb = kk * 32 + ((lane & 8) ? 16 : 0);
            #pragma unroll
            for (int jp = 0; jp < 2; jp++) {
                uint32_t off = sw128((uint32_t)((brow + jp * 16) * 128) + bkb);
                uint32_t bf[4];
                ldm_x4(bf[0], bf[1], bf[2], bf[3], sb + OFF_B + off);
                #pragma unroll
                for (int f = 0; f < 2; f++) {
                    mma_f16(acc[f][2 * jp],     a[f], bf);
                    mma_f16(acc[f][2 * jp + 1], a[f], bf + 2);
                }
            }
        }
    }

    #pragma unroll
    for (int f = 0; f < 2; f++) {
        int r0 = bm + mbase + f * 16 + (lane >> 2);
        #pragma unroll
        for (int j = 0; j < 4; j++) {
            int nloc = nwbase + j * 8 + (lane & 3) * 2;
            float s0 = SC[nloc], s1 = SC[nloc + 1];
            float t0 = SH[nloc], t1 = SH[nloc + 1];
            float v0 = acc[f][j][0] * s0 + t0;
            float v1 = acc[f][j][1] * s1 + t1;
            float v2 = acc[f][j][2] * s0 + t0;
            float v3 = acc[f][j][3] * s1 + t1;
            if (EPI != 2) {
                v0 = fmaxf(v0, 0.0f); v1 = fmaxf(v1, 0.0f);
                v2 = fmaxf(v2, 0.0f); v3 = fmaxf(v3, 0.0f);
            }
            int col = bn + nloc;
            if (EPI == 2) {
                if (r0 < N_NODES)
                    *(float2*)(C + (size_t)r0 * NB + col) = make_float2(v0, v1);
                if (r0 + 8 < N_NODES)
                    *(float2*)(C + (size_t)(r0 + 8) * NB + col) = make_float2(v2, v3);
            } else {
                __half2 p0 = __float22half2_rn(make_float2(v0, v1));
                __half2 p1 = __float22half2_rn(make_float2(v2, v3));
                if (r0 < N_NODES)
                    *(__half2*)(Ch + (size_t)r0 * NB + col) = p0;
                if (r0 + 8 < N_NODES)
                    *(__half2*)(Ch + (size_t)(r0 + 8) * NB + col) = p1;
            }
        }
    }
}

// ---------------- launch ----------------
extern "C" void kernel_launch(void* const* d_in, const int* in_sizes, int n_in,
                              void* d_out, int out_size) {
    const float* x    = (const float*)d_in[0];
    const int*   ei   = (const int*)d_in[1];
    const float* W1   = (const float*)d_in[2];
    const float* b1   = (const float*)d_in[3];
    const float* W2a  = (const float*)d_in[4];
    const float* b2a  = (const float*)d_in[5];
    const float* W2l  = (const float*)d_in[6];
    const float* b2l  = (const float*)d_in[7];
    const float* eps  = (const float*)d_in[8];
    const float* bng  = (const float*)d_in[9];
    const float* bnb  = (const float*)d_in[10];
    const float* bnm  = (const float*)d_in[11];
    const float* bnv  = (const float*)d_in[12];
    float* out = (float*)d_out;

    void* p;
    cudaGetSymbolAddress(&p, g_th);   __half* th = (__half*)p;
    cudaGetSymbolAddress(&p, g_hf16); __half* hf = (__half*)p;
    cudaGetSymbolAddress(&p, g_wf16); const __half* wf = (const __half*)p;

    const int* srcp = ei;
    const int* dstp = ei + N_EDGES;

    const int SMEM_F = 81920 + 1024;   // fused agg+gemm1
    const int SMEM_G = 25088 + 256;    // gemm2
    cudaFuncSetAttribute(aggemm_kernel,    cudaFuncAttributeMaxDynamicSharedMemorySize, SMEM_F);
    cudaFuncSetAttribute(gemm_hmma<256, 1>, cudaFuncAttributeMaxDynamicSharedMemorySize, SMEM_G);
    cudaFuncSetAttribute(gemm_hmma<128, 2>, cudaFuncAttributeMaxDynamicSharedMemorySize, SMEM_G);

    prep_kernel<<<(PR_C + 255) / 256, 256>>>(W1, W2a, W2l, x, dstp);
    scan_kernel<<<1, 1024>>>();
    fill_kernel<<<(N_EDGES + 255) / 256, 256>>>(srcp, dstp);

    dim3 g256(4, 157), g128(2, 157);
    const float RS[5] = {1.0f / 16, 1.0f / 256, 1.0f / 4096, 1.0f / 65536, 1.0f / 1048576};

    for (int i = 0; i < 4; i++) {
        aggemm_kernel<<<157, 256, SMEM_F>>>(hf, wf + (size_t)i * 65536, th,
                                            b1 + i * 256, eps, i, RS[i]);
        gemm_hmma<256, 1><<<g256, 256, SMEM_G>>>(th, wf + (size_t)(5 + i) * 65536,
                                                 nullptr, hf, b2a + i * 256,
                                                 bng + i * 256, bnb + i * 256, bnm + i * 256, bnv + i * 256,
                                                 RS[i]);
    }
    aggemm_kernel<<<157, 256, SMEM_F>>>(hf, wf + (size_t)4 * 65536, th,
                                        b1 + 4 * 256, eps, 4, RS[4]);
    gemm_hmma<128, 2><<<g128, 256, SMEM_G>>>(th, wf + (size_t)9 * 65536,
                                             out, nullptr, b2l,
                                             nullptr, nullptr, nullptr, nullptr, 1048576.0f);
}

// round 16
// speedup vs baseline: 1.3466x; 1.3308x over previous
#include <cuda_runtime.h>
#include <cuda_fp16.h>
#include <cstdint>

#define N_NODES 20000
#define N_EDGES 320000
#define DK      256
#define M_PAD   20096
#define BN_EPS  1e-5f

// ---------------- static scratch ----------------
__device__ __half g_zh[M_PAD * DK];
__device__ __half g_th[M_PAD * DK];
__device__ __half g_hf16[M_PAD * DK];
__device__ int    g_deg[N_NODES];
__device__ int    g_offs[N_NODES + 1];
__device__ int    g_cursor[N_NODES];
__device__ int    g_csrc[N_EDGES];
__device__ __half g_wf16[622592];

// ---------------- helpers ----------------
__device__ __forceinline__ uint32_t smem_u32(const void* p) {
    uint32_t a;
    asm("{ .reg .u64 t; cvta.to.shared.u64 t, %1; cvt.u32.u64 %0, t; }" : "=r"(a) : "l"(p));
    return a;
}
__device__ __forceinline__ uint32_t sw128(uint32_t off) { return off ^ ((off >> 3) & 0x70); }

__device__ __forceinline__ void ldm_x4(uint32_t& r0, uint32_t& r1, uint32_t& r2, uint32_t& r3,
                                       uint32_t addr) {
    asm volatile("ldmatrix.sync.aligned.m8n8.x4.shared.b16 {%0,%1,%2,%3}, [%4];"
                 : "=r"(r0), "=r"(r1), "=r"(r2), "=r"(r3) : "r"(addr));
}
__device__ __forceinline__ void mma_f16(float* d, const uint32_t* a, const uint32_t* b) {
    asm volatile(
        "mma.sync.aligned.m16n8k16.row.col.f32.f16.f16.f32 "
        "{%0,%1,%2,%3}, {%4,%5,%6,%7}, {%8,%9}, {%0,%1,%2,%3};"
        : "+f"(d[0]), "+f"(d[1]), "+f"(d[2]), "+f"(d[3])
        : "r"(a[0]), "r"(a[1]), "r"(a[2]), "r"(a[3]), "r"(b[0]), "r"(b[1]));
}
__device__ __forceinline__ void acc8(float2* a, uint4 b) {
    float2 t;
    t = __half22float2(*(__half2*)&b.x); a[0].x += t.x; a[0].y += t.y;
    t = __half22float2(*(__half2*)&b.y); a[1].x += t.x; a[1].y += t.y;
    t = __half22float2(*(__half2*)&b.z); a[2].x += t.x; a[2].y += t.y;
    t = __half22float2(*(__half2*)&b.w); a[3].x += t.x; a[3].y += t.y;
}

// ---------------- CSR build ----------------
__global__ void scan_kernel() {
    __shared__ int carry;
    __shared__ int wsum[32];
    int tid = threadIdx.x, lane = tid & 31, wid = tid >> 5;
    if (tid == 0) carry = 0;
    __syncthreads();
    for (int base = 0; base < N_NODES; base += 1024) {
        int i = base + tid;
        int v = (i < N_NODES) ? g_deg[i] : 0;
        int s = v;
        #pragma unroll
        for (int d = 1; d < 32; d <<= 1) {
            int t = __shfl_up_sync(0xffffffffu, s, d);
            if (lane >= d) s += t;
        }
        if (lane == 31) wsum[wid] = s;
        __syncthreads();
        if (wid == 0) {
            int ws = wsum[lane];
            #pragma unroll
            for (int d = 1; d < 32; d <<= 1) {
                int t = __shfl_up_sync(0xffffffffu, ws, d);
                if (lane >= d) ws += t;
            }
            wsum[lane] = ws;
        }
        __syncthreads();
        int excl = s - v + (wid > 0 ? wsum[wid - 1] : 0) + carry;
        if (i < N_NODES) { g_offs[i] = excl; g_cursor[i] = excl; }
        int total = wsum[31];
        __syncthreads();
        if (tid == 0) carry += total;
        __syncthreads();
    }
    if (tid == 0) g_offs[N_NODES] = carry;
}

__global__ void fill_kernel(const int* __restrict__ src, const int* __restrict__ dst) {
    int e = blockIdx.x * blockDim.x + threadIdx.x;
    if (e < N_NODES) g_deg[e] = 0;
    if (e < N_EDGES) {
        int d = dst[e];
        int pos = atomicAdd(&g_cursor[d], 1);
        g_csrc[pos] = src[e];
    }
}

// ---------------- prep: weight transpose + x pack + edge count ----------------
#define PR_W   622592
#define PR_X   (PR_W + 1280000)
#define PR_C   (PR_X + N_EDGES)
__global__ void prep_kernel(const float* __restrict__ W1, const float* __restrict__ W2a,
                            const float* __restrict__ W2l, const float* __restrict__ x,
                            const int* __restrict__ dst) {
    int i = blockIdx.x * blockDim.x + threadIdx.x;
    if (i < PR_W) {
        const float* src;
        int local, N;
        if (i < 327680)      { src = W1  + (size_t)(i >> 16) * 65536;            local = i & 65535;  N = 256; }
        else if (i < 589824) { src = W2a + (size_t)((i - 327680) >> 16) * 65536; local = (i - 327680) & 65535; N = 256; }
        else                 { src = W2l;                                        local = i - 589824; N = 128; }
        int n = local >> 8, k = local & 255;
        g_wf16[i] = __float2half_rn(src[k * N + n]);
    } else if (i < PR_X) {
        int j = i - PR_W;
        float4 v = ((const float4*)x)[j];
        __half2 p0 = __float22half2_rn(make_float2(v.x, v.y));
        __half2 p1 = __float22half2_rn(make_float2(v.z, v.w));
        ((uint2*)g_hf16)[j] = make_uint2(*(uint32_t*)&p0, *(uint32_t*)&p1);
    } else if (i < PR_C) {
        int e = i - PR_X;
        atomicAdd(&g_deg[dst[e]], 1);
    }
}

// ---------------- aggregation: f16 gather, MLP-4 unrolled, fp32 acc, x1/16 out ----------------
__global__ void agg_kernel(const __half* __restrict__ h, __half* __restrict__ z,
                           const float* __restrict__ eps, int layer) {
    int gw = (blockIdx.x * blockDim.x + threadIdx.x) >> 5;
    if (gw >= N_NODES) return;
    int lane = threadIdx.x & 31;
    float e1 = 1.0f + __ldg(&eps[layer]);
    const uint4* h4 = (const uint4*)h;

    uint4 sv = h4[(size_t)gw * 32 + lane];
    float2 a[4];
    a[0] = __half22float2(*(__half2*)&sv.x);
    a[1] = __half22float2(*(__half2*)&sv.y);
    a[2] = __half22float2(*(__half2*)&sv.z);
    a[3] = __half22float2(*(__half2*)&sv.w);
    #pragma unroll
    for (int q = 0; q < 4; q++) { a[q].x *= e1; a[q].y *= e1; }

    int beg = g_offs[gw], end = g_offs[gw + 1];
    int j = beg;
    // 4-edge unroll: 4 independent gathers in flight
    for (; j + 3 < end; j += 4) {
        int u0 = g_csrc[j], u1 = g_csrc[j + 1], u2 = g_csrc[j + 2], u3 = g_csrc[j + 3];
        uint4 b0 = h4[(size_t)u0 * 32 + lane];
        uint4 b1 = h4[(size_t)u1 * 32 + lane];
        uint4 b2 = h4[(size_t)u2 * 32 + lane];
        uint4 b3 = h4[(size_t)u3 * 32 + lane];
        acc8(a, b0); acc8(a, b1); acc8(a, b2); acc8(a, b3);
    }
    for (; j < end; j++) {
        uint4 b = h4[(size_t)g_csrc[j] * 32 + lane];
        acc8(a, b);
    }
    const float S = 0.0625f;
    #pragma unroll
    for (int q = 0; q < 4; q++) { a[q].x *= S; a[q].y *= S; }
    __half2 o0 = __float22half2_rn(a[0]), o1 = __float22half2_rn(a[1]);
    __half2 o2 = __float22half2_rn(a[2]), o3 = __float22half2_rn(a[3]);
    ((uint4*)z)[(size_t)gw * 32 + lane] =
        make_uint4(*(uint32_t*)&o0, *(uint32_t*)&o1, *(uint32_t*)&o2, *(uint32_t*)&o3);
}

// ---------------- fp16 HMMA GEMM, tile 128(M)x64(N), single-term ----------------
// EPI 0: relu(acc + bias*rs) -> f16 ; EPI 1: relu(BN) -> f16 ; EPI 2: acc*rs + bias -> f32
template <int NB, int EPI>
__global__ __launch_bounds__(256, 2)
void gemm_hmma(const __half* __restrict__ A, const __half* __restrict__ B,
               float* __restrict__ C, __half* __restrict__ Ch,
               const float* __restrict__ bias,
               const float* __restrict__ bn_g, const float* __restrict__ bn_b,
               const float* __restrict__ bn_m, const float* __restrict__ bn_v,
               float rs) {
    extern __shared__ __align__(1024) char smem[];
    constexpr int OFF_A  = 0;
    constexpr int OFF_B  = 16384;
    constexpr int OFF_SC = 24576;
    constexpr int OFF_SH = 24832;

    const int tid = threadIdx.x, wid = tid >> 5, lane = tid & 31;
    const int warpM = wid >> 1, warpN = wid & 1;
    const int bm = blockIdx.y * 128, bn = blockIdx.x * 64;
    const uint32_t sb = smem_u32(smem);

    float* SC = (float*)(smem + OFF_SC);
    float* SH = (float*)(smem + OFF_SH);
    if (tid < 64) {
        int n = bn + tid;
        if (EPI == 1) {
            float s = bn_g[n] * rsqrtf(bn_v[n] + BN_EPS);
            SC[tid] = s;
            SH[tid] = ((bias[n] - bn_m[n]) * s + bn_b[n]) * rs;
        } else if (EPI == 0) {
            SC[tid] = 1.0f;
            SH[tid] = bias[n] * rs;
        } else {
            SC[tid] = rs;
            SH[tid] = bias[n];
        }
    }

    float acc[2][4][4];
    #pragma unroll
    for (int f = 0; f < 2; f++)
        #pragma unroll
        for (int j = 0; j < 4; j++)
            #pragma unroll
            for (int q = 0; q < 4; q++) acc[f][j][q] = 0.0f;

    const int mbase = warpM * 32, nwbase = warpN * 32;

    for (int kc = 0; kc < 4; kc++) {
        __syncthreads();
        #pragma unroll
        for (int it = 0; it < 4; it++) {
            int item = tid + it * 256;
            int r = item >> 3, g = item & 7;
            uint4 v = *(const uint4*)(A + (size_t)(bm + r) * DK + kc * 64 + g * 8);
            *(uint4*)(smem + OFF_A + sw128((uint32_t)(r * 128 + g * 16))) = v;
        }
        #pragma unroll
        for (int it = 0; it < 2; it++) {
            int item = tid + it * 256;
            int n = item >> 3, g = item & 7;
            uint4 v = *(const uint4*)(B + (size_t)(bn + n) * DK + kc * 64 + g * 8);
            *(uint4*)(smem + OFF_B + sw128((uint32_t)(n * 128 + g * 16))) = v;
        }
        __syncthreads();

        #pragma unroll
        for (int kk = 0; kk < 4; kk++) {
            uint32_t a[2][4];
            int arow = mbase + (lane & 15);
            uint32_t akb = kk * 32 + ((lane & 16) ? 16 : 0);
            #pragma unroll
            for (int f = 0; f < 2; f++) {
                uint32_t off = sw128((uint32_t)((arow + f * 16) * 128) + akb);
                ldm_x4(a[f][0], a[f][1], a[f][2], a[f][3], sb + OFF_A + off);
            }
            int brow = nwbase + (lane & 7) + ((lane & 16) ? 8 : 0);
            uint32_t bkb = kk * 32 + ((lane & 8) ? 16 : 0);
            #pragma unroll
            for (int jp = 0; jp < 2; jp++) {
                uint32_t off = sw128((uint32_t)((brow + jp * 16) * 128) + bkb);
                uint32_t bf[4];
                ldm_x4(bf[0], bf[1], bf[2], bf[3], sb + OFF_B + off);
                #pragma unroll
                for (int f = 0; f < 2; f++) {
                    mma_f16(acc[f][2 * jp],     a[f], bf);
                    mma_f16(acc[f][2 * jp + 1], a[f], bf + 2);
                }
            }
        }
    }

    #pragma unroll
    for (int f = 0; f < 2; f++) {
        int r0 = bm + mbase + f * 16 + (lane >> 2);
        #pragma unroll
        for (int j = 0; j < 4; j++) {
            int nloc = nwbase + j * 8 + (lane & 3) * 2;
            float s0 = SC[nloc], s1 = SC[nloc + 1];
            float t0 = SH[nloc], t1 = SH[nloc + 1];
            float v0 = acc[f][j][0] * s0 + t0;
            float v1 = acc[f][j][1] * s1 + t1;
            float v2 = acc[f][j][2] * s0 + t0;
            float v3 = acc[f][j][3] * s1 + t1;
            if (EPI != 2) {
                v0 = fmaxf(v0, 0.0f); v1 = fmaxf(v1, 0.0f);
                v2 = fmaxf(v2, 0.0f); v3 = fmaxf(v3, 0.0f);
            }
            int col = bn + nloc;
            if (EPI == 2) {
                if (r0 < N_NODES)
                    *(float2*)(C + (size_t)r0 * NB + col) = make_float2(v0, v1);
                if (r0 + 8 < N_NODES)
                    *(float2*)(C + (size_t)(r0 + 8) * NB + col) = make_float2(v2, v3);
            } else {
                __half2 p0 = __float22half2_rn(make_float2(v0, v1));
                __half2 p1 = __float22half2_rn(make_float2(v2, v3));
                if (r0 < N_NODES)
                    *(__half2*)(Ch + (size_t)r0 * NB + col) = p0;
                if (r0 + 8 < N_NODES)
                    *(__half2*)(Ch + (size_t)(r0 + 8) * NB + col) = p1;
            }
        }
    }
}

// ---------------- launch ----------------
extern "C" void kernel_launch(void* const* d_in, const int* in_sizes, int n_in,
                              void* d_out, int out_size) {
    const float* x    = (const float*)d_in[0];
    const int*   ei   = (const int*)d_in[1];
    const float* W1   = (const float*)d_in[2];
    const float* b1   = (const float*)d_in[3];
    const float* W2a  = (const float*)d_in[4];
    const float* b2a  = (const float*)d_in[5];
    const float* W2l  = (const float*)d_in[6];
    const float* b2l  = (const float*)d_in[7];
    const float* eps  = (const float*)d_in[8];
    const float* bng  = (const float*)d_in[9];
    const float* bnb  = (const float*)d_in[10];
    const float* bnm  = (const float*)d_in[11];
    const float* bnv  = (const float*)d_in[12];
    float* out = (float*)d_out;

    void* p;
    cudaGetSymbolAddress(&p, g_zh);   __half* zh = (__half*)p;
    cudaGetSymbolAddress(&p, g_th);   __half* th = (__half*)p;
    cudaGetSymbolAddress(&p, g_hf16); __half* hf = (__half*)p;
    cudaGetSymbolAddress(&p, g_wf16); const __half* wf = (const __half*)p;

    const int* srcp = ei;
    const int* dstp = ei + N_EDGES;

    const int SMEM = 25088 + 256;
    cudaFuncSetAttribute(gemm_hmma<256, 0>, cudaFuncAttributeMaxDynamicSharedMemorySize, SMEM);
    cudaFuncSetAttribute(gemm_hmma<256, 1>, cudaFuncAttributeMaxDynamicSharedMemorySize, SMEM);
    cudaFuncSetAttribute(gemm_hmma<128, 2>, cudaFuncAttributeMaxDynamicSharedMemorySize, SMEM);

    prep_kernel<<<(PR_C + 255) / 256, 256>>>(W1, W2a, W2l, x, dstp);
    scan_kernel<<<1, 1024>>>();
    fill_kernel<<<(N_EDGES + 255) / 256, 256>>>(srcp, dstp);

    dim3 g256(4, 157), g128(2, 157);
    const float RS[5] = {1.0f / 16, 1.0f / 256, 1.0f / 4096, 1.0f / 65536, 1.0f / 1048576};

    for (int i = 0; i < 4; i++) {
        agg_kernel<<<2500, 256>>>(hf, zh, eps, i);
        gemm_hmma<256, 0><<<g256, 256, SMEM>>>(zh, wf + (size_t)i * 65536,
                                               nullptr, th, b1 + i * 256,
                                               nullptr, nullptr, nullptr, nullptr, RS[i]);
        gemm_hmma<256, 1><<<g256, 256, SMEM>>>(th, wf + (size_t)(5 + i) * 65536,
                                               nullptr, hf, b2a + i * 256,
                                               bng + i * 256, bnb + i * 256, bnm + i * 256, bnv + i * 256,
                                               RS[i]);
    }
    agg_kernel<<<2500, 256>>>(hf, zh, eps, 4);
    gemm_hmma<256, 0><<<g256, 256, SMEM>>>(zh, wf + (size_t)4 * 65536,
                                           nullptr, th, b1 + 4 * 256,
                                           nullptr, nullptr, nullptr, nullptr, RS[4]);
    gemm_hmma<128, 2><<<g128, 256, SMEM>>>(th, wf + (size_t)9 * 65536,
                                           out, nullptr, b2l,
                                           nullptr, nullptr, nullptr, nullptr, 1048576.0f);
}

// round 17
// speedup vs baseline: 1.4111x; 1.0479x over previous
#include <cuda_runtime.h>
#include <cuda_fp16.h>
#include <cstdint>

#define N_NODES 20000
#define N_EDGES 320000
#define DK      256
#define M_PAD   20096
#define BN_EPS  1e-5f

// ---------------- static scratch ----------------
__device__ __half g_zh[M_PAD * DK];
__device__ __half g_th[M_PAD * DK];
__device__ __half g_hf16[M_PAD * DK];
__device__ int    g_deg[N_NODES];
__device__ int    g_offs[N_NODES + 1];
__device__ int    g_cursor[N_NODES];
__device__ int    g_csrc[N_EDGES];
__device__ __half g_wf16[622592];

// ---------------- helpers ----------------
__device__ __forceinline__ uint32_t smem_u32(const void* p) {
    uint32_t a;
    asm("{ .reg .u64 t; cvta.to.shared.u64 t, %1; cvt.u32.u64 %0, t; }" : "=r"(a) : "l"(p));
    return a;
}
__device__ __forceinline__ uint32_t sw128(uint32_t off) { return off ^ ((off >> 3) & 0x70); }

__device__ __forceinline__ void ldm_x4(uint32_t& r0, uint32_t& r1, uint32_t& r2, uint32_t& r3,
                                       uint32_t addr) {
    asm volatile("ldmatrix.sync.aligned.m8n8.x4.shared.b16 {%0,%1,%2,%3}, [%4];"
                 : "=r"(r0), "=r"(r1), "=r"(r2), "=r"(r3) : "r"(addr));
}
__device__ __forceinline__ void mma_f16(float* d, const uint32_t* a, const uint32_t* b) {
    asm volatile(
        "mma.sync.aligned.m16n8k16.row.col.f32.f16.f16.f32 "
        "{%0,%1,%2,%3}, {%4,%5,%6,%7}, {%8,%9}, {%0,%1,%2,%3};"
        : "+f"(d[0]), "+f"(d[1]), "+f"(d[2]), "+f"(d[3])
        : "r"(a[0]), "r"(a[1]), "r"(a[2]), "r"(a[3]), "r"(b[0]), "r"(b[1]));
}
__device__ __forceinline__ void acc8(float2* a, uint4 b) {
    float2 t;
    t = __half22float2(*(__half2*)&b.x); a[0].x += t.x; a[0].y += t.y;
    t = __half22float2(*(__half2*)&b.y); a[1].x += t.x; a[1].y += t.y;
    t = __half22float2(*(__half2*)&b.z); a[2].x += t.x; a[2].y += t.y;
    t = __half22float2(*(__half2*)&b.w); a[3].x += t.x; a[3].y += t.y;
}
// pairwise fp16 add of two gathered rows (one fp16 rounding level)
__device__ __forceinline__ uint4 hpair(uint4 x, uint4 y) {
    uint4 r;
    *(__half2*)&r.x = __hadd2(*(__half2*)&x.x, *(__half2*)&y.x);
    *(__half2*)&r.y = __hadd2(*(__half2*)&x.y, *(__half2*)&y.y);
    *(__half2*)&r.z = __hadd2(*(__half2*)&x.z, *(__half2*)&y.z);
    *(__half2*)&r.w = __hadd2(*(__half2*)&x.w, *(__half2*)&y.w);
    return r;
}

// ---------------- CSR build ----------------
__global__ void scan_kernel() {
    __shared__ int carry;
    __shared__ int wsum[32];
    int tid = threadIdx.x, lane = tid & 31, wid = tid >> 5;
    if (tid == 0) carry = 0;
    __syncthreads();
    for (int base = 0; base < N_NODES; base += 1024) {
        int i = base + tid;
        int v = (i < N_NODES) ? g_deg[i] : 0;
        int s = v;
        #pragma unroll
        for (int d = 1; d < 32; d <<= 1) {
            int t = __shfl_up_sync(0xffffffffu, s, d);
            if (lane >= d) s += t;
        }
        if (lane == 31) wsum[wid] = s;
        __syncthreads();
        if (wid == 0) {
            int ws = wsum[lane];
            #pragma unroll
            for (int d = 1; d < 32; d <<= 1) {
                int t = __shfl_up_sync(0xffffffffu, ws, d);
                if (lane >= d) ws += t;
            }
            wsum[lane] = ws;
        }
        __syncthreads();
        int excl = s - v + (wid > 0 ? wsum[wid - 1] : 0) + carry;
        if (i < N_NODES) { g_offs[i] = excl; g_cursor[i] = excl; }
        int total = wsum[31];
        __syncthreads();
        if (tid == 0) carry += total;
        __syncthreads();
    }
    if (tid == 0) g_offs[N_NODES] = carry;
}

__global__ void fill_kernel(const int* __restrict__ src, const int* __restrict__ dst) {
    int e = blockIdx.x * blockDim.x + threadIdx.x;
    if (e < N_NODES) g_deg[e] = 0;
    if (e < N_EDGES) {
        int d = dst[e];
        int pos = atomicAdd(&g_cursor[d], 1);
        g_csrc[pos] = src[e];
    }
}

// ---------------- prep: weight transpose + x pack + edge count ----------------
#define PR_W   622592
#define PR_X   (PR_W + 1280000)
#define PR_C   (PR_X + N_EDGES)
__global__ void prep_kernel(const float* __restrict__ W1, const float* __restrict__ W2a,
                            const float* __restrict__ W2l, const float* __restrict__ x,
                            const int* __restrict__ dst) {
    int i = blockIdx.x * blockDim.x + threadIdx.x;
    if (i < PR_W) {
        const float* src;
        int local, N;
        if (i < 327680)      { src = W1  + (size_t)(i >> 16) * 65536;            local = i & 65535;  N = 256; }
        else if (i < 589824) { src = W2a + (size_t)((i - 327680) >> 16) * 65536; local = (i - 327680) & 65535; N = 256; }
        else                 { src = W2l;                                        local = i - 589824; N = 128; }
        int n = local >> 8, k = local & 255;
        g_wf16[i] = __float2half_rn(src[k * N + n]);
    } else if (i < PR_X) {
        int j = i - PR_W;
        float4 v = ((const float4*)x)[j];
        __half2 p0 = __float22half2_rn(make_float2(v.x, v.y));
        __half2 p1 = __float22half2_rn(make_float2(v.z, v.w));
        ((uint2*)g_hf16)[j] = make_uint2(*(uint32_t*)&p0, *(uint32_t*)&p1);
    } else if (i < PR_C) {
        int e = i - PR_X;
        atomicAdd(&g_deg[dst[e]], 1);
    }
}

// ---------------- aggregation: f16 gather, MLP-4, pairwise HADD2 pre-reduce ----------------
__global__ void agg_kernel(const __half* __restrict__ h, __half* __restrict__ z,
                           const float* __restrict__ eps, int layer) {
    int gw = (blockIdx.x * blockDim.x + threadIdx.x) >> 5;
    if (gw >= N_NODES) return;
    int lane = threadIdx.x & 31;
    float e1 = 1.0f + __ldg(&eps[layer]);
    const uint4* h4 = (const uint4*)h;

    uint4 sv = h4[(size_t)gw * 32 + lane];
    float2 a[4];
    a[0] = __half22float2(*(__half2*)&sv.x);
    a[1] = __half22float2(*(__half2*)&sv.y);
    a[2] = __half22float2(*(__half2*)&sv.z);
    a[3] = __half22float2(*(__half2*)&sv.w);
    #pragma unroll
    for (int q = 0; q < 4; q++) { a[q].x *= e1; a[q].y *= e1; }

    int beg = g_offs[gw], end = g_offs[gw + 1];
    int j = beg;
    // 4 edges in flight; pairwise fp16 add, then fp32 accumulate (one fp16 rounding level)
    for (; j + 3 < end; j += 4) {
        int u0 = g_csrc[j], u1 = g_csrc[j + 1], u2 = g_csrc[j + 2], u3 = g_csrc[j + 3];
        uint4 b0 = h4[(size_t)u0 * 32 + lane];
        uint4 b1 = h4[(size_t)u1 * 32 + lane];
        uint4 b2 = h4[(size_t)u2 * 32 + lane];
        uint4 b3 = h4[(size_t)u3 * 32 + lane];
        acc8(a, hpair(b0, b1));
        acc8(a, hpair(b2, b3));
    }
    if (j + 1 < end) {
        int u0 = g_csrc[j], u1 = g_csrc[j + 1];
        uint4 b0 = h4[(size_t)u0 * 32 + lane];
        uint4 b1 = h4[(size_t)u1 * 32 + lane];
        acc8(a, hpair(b0, b1));
        j += 2;
    }
    if (j < end) {
        uint4 b = h4[(size_t)g_csrc[j] * 32 + lane];
        acc8(a, b);
    }
    const float S = 0.0625f;
    #pragma unroll
    for (int q = 0; q < 4; q++) { a[q].x *= S; a[q].y *= S; }
    __half2 o0 = __float22half2_rn(a[0]), o1 = __float22half2_rn(a[1]);
    __half2 o2 = __float22half2_rn(a[2]), o3 = __float22half2_rn(a[3]);
    ((uint4*)z)[(size_t)gw * 32 + lane] =
        make_uint4(*(uint32_t*)&o0, *(uint32_t*)&o1, *(uint32_t*)&o2, *(uint32_t*)&o3);
}

// ---------------- fp16 HMMA GEMM, tile 128(M)x64(N), single-term ----------------
// EPI 0: relu(acc + bias*rs) -> f16 ; EPI 1: relu(BN) -> f16 ; EPI 2: acc*rs + bias -> f32
template <int NB, int EPI>
__global__ __launch_bounds__(256, 2)
void gemm_hmma(const __half* __restrict__ A, const __half* __restrict__ B,
               float* __restrict__ C, __half* __restrict__ Ch,
               const float* __restrict__ bias,
               const float* __restrict__ bn_g, const float* __restrict__ bn_b,
               const float* __restrict__ bn_m, const float* __restrict__ bn_v,
               float rs) {
    extern __shared__ __align__(1024) char smem[];
    constexpr int OFF_A  = 0;
    constexpr int OFF_B  = 16384;
    constexpr int OFF_SC = 24576;
    constexpr int OFF_SH = 24832;

    const int tid = threadIdx.x, wid = tid >> 5, lane = tid & 31;
    const int warpM = wid >> 1, warpN = wid & 1;
    const int bm = blockIdx.y * 128, bn = blockIdx.x * 64;
    const uint32_t sb = smem_u32(smem);

    float* SC = (float*)(smem + OFF_SC);
    float* SH = (float*)(smem + OFF_SH);
    if (tid < 64) {
        int n = bn + tid;
        if (EPI == 1) {
            float s = bn_g[n] * rsqrtf(bn_v[n] + BN_EPS);
            SC[tid] = s;
            SH[tid] = ((bias[n] - bn_m[n]) * s + bn_b[n]) * rs;
        } else if (EPI == 0) {
            SC[tid] = 1.0f;
            SH[tid] = bias[n] * rs;
        } else {
            SC[tid] = rs;
            SH[tid] = bias[n];
        }
    }

    float acc[2][4][4];
    #pragma unroll
    for (int f = 0; f < 2; f++)
        #pragma unroll
        for (int j = 0; j < 4; j++)
            #pragma unroll
            for (int q = 0; q < 4; q++) acc[f][j][q] = 0.0f;

    const int mbase = warpM * 32, nwbase = warpN * 32;

    for (int kc = 0; kc < 4; kc++) {
        __syncthreads();
        #pragma unroll
        for (int it = 0; it < 4; it++) {
            int item = tid + it * 256;
            int r = item >> 3, g = item & 7;
            uint4 v = *(const uint4*)(A + (size_t)(bm + r) * DK + kc * 64 + g * 8);
            *(uint4*)(smem + OFF_A + sw128((uint32_t)(r * 128 + g * 16))) = v;
        }
        #pragma unroll
        for (int it = 0; it < 2; it++) {
            int item = tid + it * 256;
            int n = item >> 3, g = item & 7;
            uint4 v = *(const uint4*)(B + (size_t)(bn + n) * DK + kc * 64 + g * 8);
            *(uint4*)(smem + OFF_B + sw128((uint32_t)(n * 128 + g * 16))) = v;
        }
        __syncthreads();

        #pragma unroll
        for (int kk = 0; kk < 4; kk++) {
            uint32_t a[2][4];
            int arow = mbase + (lane & 15);
            uint32_t akb = kk * 32 + ((lane & 16) ? 16 : 0);
            #pragma unroll
            for (int f = 0; f < 2; f++) {
                uint32_t off = sw128((uint32_t)((arow + f * 16) * 128) + akb);
                ldm_x4(a[f][0], a[f][1], a[f][2], a[f][3], sb + OFF_A + off);
            }
            int brow = nwbase + (lane & 7) + ((lane & 16) ? 8 : 0);
            uint32_t bkb = kk * 32 + ((lane & 8) ? 16 : 0);
            #pragma unroll
            for (int jp = 0; jp < 2; jp++) {
                uint32_t off = sw128((uint32_t)((brow + jp * 16) * 128) + bkb);
                uint32_t bf[4];
                ldm_x4(bf[0], bf[1], bf[2], bf[3], sb + OFF_B + off);
                #pragma unroll
                for (int f = 0; f < 2; f++) {
                    mma_f16(acc[f][2 * jp],     a[f], bf);
                    mma_f16(acc[f][2 * jp + 1], a[f], bf + 2);
                }
            }
        }
    }

    #pragma unroll
    for (int f = 0; f < 2; f++) {
        int r0 = bm + mbase + f * 16 + (lane >> 2);
        #pragma unroll
        for (int j = 0; j < 4; j++) {
            int nloc = nwbase + j * 8 + (lane & 3) * 2;
            float s0 = SC[nloc], s1 = SC[nloc + 1];
            float t0 = SH[nloc], t1 = SH[nloc + 1];
            float v0 = acc[f][j][0] * s0 + t0;
            float v1 = acc[f][j][1] * s1 + t1;
            float v2 = acc[f][j][2] * s0 + t0;
            float v3 = acc[f][j][3] * s1 + t1;
            if (EPI != 2) {
                v0 = fmaxf(v0, 0.0f); v1 = fmaxf(v1, 0.0f);
                v2 = fmaxf(v2, 0.0f); v3 = fmaxf(v3, 0.0f);
            }
            int col = bn + nloc;
            if (EPI == 2) {
                if (r0 < N_NODES)
                    *(float2*)(C + (size_t)r0 * NB + col) = make_float2(v0, v1);
                if (r0 + 8 < N_NODES)
                    *(float2*)(C + (size_t)(r0 + 8) * NB + col) = make_float2(v2, v3);
            } else {
                __half2 p0 = __float22half2_rn(make_float2(v0, v1));
                __half2 p1 = __float22half2_rn(make_float2(v2, v3));
                if (r0 < N_NODES)
                    *(__half2*)(Ch + (size_t)r0 * NB + col) = p0;
                if (r0 + 8 < N_NODES)
                    *(__half2*)(Ch + (size_t)(r0 + 8) * NB + col) = p1;
            }
        }
    }
}

// ---------------- launch ----------------
extern "C" void kernel_launch(void* const* d_in, const int* in_sizes, int n_in,
                              void* d_out, int out_size) {
    const float* x    = (const float*)d_in[0];
    const int*   ei   = (const int*)d_in[1];
    const float* W1   = (const float*)d_in[2];
    const float* b1   = (const float*)d_in[3];
    const float* W2a  = (const float*)d_in[4];
    const float* b2a  = (const float*)d_in[5];
    const float* W2l  = (const float*)d_in[6];
    const float* b2l  = (const float*)d_in[7];
    const float* eps  = (const float*)d_in[8];
    const float* bng  = (const float*)d_in[9];
    const float* bnb  = (const float*)d_in[10];
    const float* bnm  = (const float*)d_in[11];
    const float* bnv  = (const float*)d_in[12];
    float* out = (float*)d_out;

    void* p;
    cudaGetSymbolAddress(&p, g_zh);   __half* zh = (__half*)p;
    cudaGetSymbolAddress(&p, g_th);   __half* th = (__half*)p;
    cudaGetSymbolAddress(&p, g_hf16); __half* hf = (__half*)p;
    cudaGetSymbolAddress(&p, g_wf16); const __half* wf = (const __half*)p;

    const int* srcp = ei;
    const int* dstp = ei + N_EDGES;

    const int SMEM = 25088 + 256;
    cudaFuncSetAttribute(gemm_hmma<256, 0>, cudaFuncAttributeMaxDynamicSharedMemorySize, SMEM);
    cudaFuncSetAttribute(gemm_hmma<256, 1>, cudaFuncAttributeMaxDynamicSharedMemorySize, SMEM);
    cudaFuncSetAttribute(gemm_hmma<128, 2>, cudaFuncAttributeMaxDynamicSharedMemorySize, SMEM);

    prep_kernel<<<(PR_C + 255) / 256, 256>>>(W1, W2a, W2l, x, dstp);
    scan_kernel<<<1, 1024>>>();
    fill_kernel<<<(N_EDGES + 255) / 256, 256>>>(srcp, dstp);

    dim3 g256(4, 157), g128(2, 157);
    const float RS[5] = {1.0f / 16, 1.0f / 256, 1.0f / 4096, 1.0f / 65536, 1.0f / 1048576};

    for (int i = 0; i < 4; i++) {
        agg_kernel<<<2500, 256>>>(hf, zh, eps, i);
        gemm_hmma<256, 0><<<g256, 256, SMEM>>>(zh, wf + (size_t)i * 65536,
                                               nullptr, th, b1 + i * 256,
                                               nullptr, nullptr, nullptr, nullptr, RS[i]);
        gemm_hmma<256, 1><<<g256, 256, SMEM>>>(th, wf + (size_t)(5 + i) * 65536,
                                               nullptr, hf, b2a + i * 256,
                                               bng + i * 256, bnb + i * 256, bnm + i * 256, bnv + i * 256,
                                               RS[i]);
    }
    agg_kernel<<<2500, 256>>>(hf, zh, eps, 4);
    gemm_hmma<256, 0><<<g256, 256, SMEM>>>(zh, wf + (size_t)4 * 65536,
                                           nullptr, th, b1 + 4 * 256,
                                           nullptr, nullptr, nullptr, nullptr, RS[4]);
    gemm_hmma<128, 2><<<g128, 256, SMEM>>>(th, wf + (size_t)9 * 65536,
                                           out, nullptr, b2l,
                                           nullptr, nullptr, nullptr, nullptr, 1048576.0f);
}